// round 2
// baseline (speedup 1.0000x reference)
#include <cuda_runtime.h>

#define TT 512
#define BD 2
#define TOK 256
#define TPR 12
#define HID 32
#define INNER 256
#define ATT_SCALE 0.0625f
#define BN_EPS 1e-5f

// ---------------- scratch (device globals: no allocation allowed) ----------
__device__ float g_w1f[TPR * HID];
__device__ float g_c1[HID];
__device__ float g_w2f[HID * TOK];
__device__ float g_c2[TOK];
__device__ float g_xb[BD * TT * TOK];          // x + bias
__device__ float g_qkv[BD * TT * 3 * INNER];   // q|k|v
__device__ float g_dots[BD * TT * TT];         // attention scores -> probs

// ---------------- f32x2 helpers (Blackwell packed fp32) --------------------
typedef unsigned long long u64;
__device__ __forceinline__ u64 pack2(float x, float y) {
    u64 r; asm("mov.b64 %0,{%1,%2};" : "=l"(r) : "f"(x), "f"(y)); return r;
}
__device__ __forceinline__ u64 fma2(u64 a, u64 b, u64 c) {
    u64 d; asm("fma.rn.f32x2 %0,%1,%2,%3;" : "=l"(d) : "l"(a), "l"(b), "l"(c)); return d;
}
__device__ __forceinline__ void unpack2(u64 v, float& x, float& y) {
    asm("mov.b64 {%0,%1},%2;" : "=f"(x), "=f"(y) : "l"(v));
}

// ---------------- setup: fold BN (eval) into weights ----------------------
__global__ void setup_kernel(const float* __restrict__ w1, const float* __restrict__ b1,
                             const float* __restrict__ g1, const float* __restrict__ be1,
                             const float* __restrict__ m1, const float* __restrict__ v1,
                             const float* __restrict__ w2, const float* __restrict__ b2,
                             const float* __restrict__ g2, const float* __restrict__ be2,
                             const float* __restrict__ m2, const float* __restrict__ v2) {
    __shared__ float A1s[HID], A2s[TOK];
    int tid = threadIdx.x;
    if (tid < HID) {
        float a = g1[tid] * rsqrtf(v1[tid] + BN_EPS);
        A1s[tid] = a;
        g_c1[tid] = (b1[tid] - m1[tid]) * a + be1[tid];
    }
    if (tid < TOK) {
        float a = g2[tid] * rsqrtf(v2[tid] + BN_EPS);
        A2s[tid] = a;
        g_c2[tid] = (b2[tid] - m2[tid]) * a + be2[tid];
    }
    __syncthreads();
    for (int i = tid; i < TPR * HID; i += blockDim.x) g_w1f[i] = w1[i] * A1s[i % HID];
    for (int i = tid; i < HID * TOK; i += blockDim.x) g_w2f[i] = w2[i] * A2s[i % TOK];
}

// ---------------- fused TPR MLP + max + (x+bias) ---------------------------
// One block per (b,s). Phase A: h1[t][:] for all 512 t into SMEM (transposed
// [h][t]). Phase B: thread c computes max_t <h1[t,:], w2[:,c]> with f32x2.
extern __shared__ float smem_f[];
__global__ __launch_bounds__(256, 2)
void fused_tpr_kernel(const float* __restrict__ r, const float* __restrict__ x) {
    float* h1t = smem_f;              // [HID][TT]
    float* W1s = smem_f + HID * TT;   // [TPR*HID]
    float* C1s = W1s + TPR * HID;     // [HID]
    const int tid = threadIdx.x;
    const int bs = blockIdx.x;        // b*TT + s

    // FIX (R1 bug): TPR*HID=384 > 256 threads -> must loop, not predicate.
    for (int i = tid; i < TPR * HID; i += 256) W1s[i] = g_w1f[i];
    if (tid < HID) C1s[tid] = g_c1[tid];
    __syncthreads();

    // Phase A: stage-1 MLP, 2 t-rows per thread
    const float* rbase = r + (size_t)bs * TT * TPR;
#pragma unroll
    for (int tt = 0; tt < 2; tt++) {
        int t = tid + tt * 256;
        float rv[TPR];
#pragma unroll
        for (int d = 0; d < TPR; d++) rv[d] = rbase[(size_t)t * TPR + d];
#pragma unroll
        for (int h = 0; h < HID; h++) {
            float acc = C1s[h];
#pragma unroll
            for (int d = 0; d < TPR; d++) acc = fmaf(rv[d], W1s[d * HID + h], acc);
            h1t[h * TT + t] = fmaxf(acc, 0.f);
        }
    }
    __syncthreads();

    // Phase B: stage-2 + max over t. Thread owns channel c = tid.
    const int c = tid;
    u64 ww[HID];
#pragma unroll
    for (int h = 0; h < HID; h++) {
        float w = g_w2f[h * TOK + c];
        ww[h] = pack2(w, w);
    }
    float mx = -3.4e38f;
    for (int t0 = 0; t0 < TT; t0 += 4) {
        u64 acc0 = 0ull, acc1 = 0ull;
#pragma unroll
        for (int h = 0; h < HID; h++) {
            double2 p = *reinterpret_cast<const double2*>(&h1t[h * TT + t0]);
            acc0 = fma2(__double_as_longlong(p.x), ww[h], acc0);
            acc1 = fma2(__double_as_longlong(p.y), ww[h], acc1);
        }
        float v0, v1, v2, v3;
        unpack2(acc0, v0, v1);
        unpack2(acc1, v2, v3);
        mx = fmaxf(mx, fmaxf(fmaxf(v0, v1), fmaxf(v2, v3)));
    }
    float bias = fmaxf(mx + g_c2[c], 0.f);
    g_xb[(size_t)bs * TOK + c] = x[(size_t)bs * TOK + c] + bias;
}

// ---------------- qkv = xb @ w_qkv  [1024,256]x[256,768] ------------------
__global__ void qkv_kernel(const float* __restrict__ w_qkv) {
    __shared__ float As[16][64];
    __shared__ float Bs[16][64];
    const int tid = threadIdx.x;
    const int tx = tid & 15, ty = tid >> 4;
    const int m0 = blockIdx.y * 64, n0 = blockIdx.x * 64;
    float acc[4][4] = {};
    for (int k0 = 0; k0 < TOK; k0 += 16) {
#pragma unroll
        for (int i = 0; i < 4; i++) {
            int idx = tid + i * 256;
            int row = idx >> 4, kk = idx & 15;
            As[kk][row] = g_xb[(size_t)(m0 + row) * TOK + k0 + kk];
            int bk = idx >> 6, bn = idx & 63;
            Bs[bk][bn] = w_qkv[(size_t)(k0 + bk) * 768 + n0 + bn];
        }
        __syncthreads();
#pragma unroll
        for (int kk = 0; kk < 16; kk++) {
            float a[4], b[4];
#pragma unroll
            for (int i = 0; i < 4; i++) { a[i] = As[kk][ty * 4 + i]; b[i] = Bs[kk][tx * 4 + i]; }
#pragma unroll
            for (int i = 0; i < 4; i++)
#pragma unroll
                for (int j = 0; j < 4; j++) acc[i][j] = fmaf(a[i], b[j], acc[i][j]);
        }
        __syncthreads();
    }
#pragma unroll
    for (int i = 0; i < 4; i++)
#pragma unroll
        for (int j = 0; j < 4; j++)
            g_qkv[(size_t)(m0 + ty * 4 + i) * 768 + n0 + tx * 4 + j] = acc[i][j];
}

// ---------------- dots = q @ k^T * scale ----------------------------------
__global__ void dots_kernel() {
    __shared__ float As[16][64];
    __shared__ float Bs[16][64];
    const int tid = threadIdx.x;
    const int tx = tid & 15, ty = tid >> 4;
    const int b = blockIdx.z;
    const int m0 = blockIdx.x * 64, n0 = blockIdx.y * 64;
    const float* q = g_qkv + (size_t)b * TT * 768;
    const float* k = g_qkv + (size_t)b * TT * 768 + INNER;
    float acc[4][4] = {};
    for (int k0 = 0; k0 < INNER; k0 += 16) {
#pragma unroll
        for (int i = 0; i < 4; i++) {
            int idx = tid + i * 256;
            int row = idx >> 4, kk = idx & 15;
            As[kk][row] = q[(size_t)(m0 + row) * 768 + k0 + kk];
            Bs[kk][row] = k[(size_t)(n0 + row) * 768 + k0 + kk];
        }
        __syncthreads();
#pragma unroll
        for (int kk = 0; kk < 16; kk++) {
            float a[4], bb[4];
#pragma unroll
            for (int i = 0; i < 4; i++) { a[i] = As[kk][ty * 4 + i]; bb[i] = Bs[kk][tx * 4 + i]; }
#pragma unroll
            for (int i = 0; i < 4; i++)
#pragma unroll
                for (int j = 0; j < 4; j++) acc[i][j] = fmaf(a[i], bb[j], acc[i][j]);
        }
        __syncthreads();
    }
    float* dst = g_dots + (size_t)b * TT * TT;
#pragma unroll
    for (int i = 0; i < 4; i++)
#pragma unroll
        for (int j = 0; j < 4; j++)
            dst[(size_t)(m0 + ty * 4 + i) * TT + n0 + tx * 4 + j] = acc[i][j] * ATT_SCALE;
}

// ---------------- row softmax over 512 -------------------------------------
__global__ void softmax_kernel() {
    const int row = blockIdx.x;
    float* p = g_dots + (size_t)row * TT;
    const int tid = threadIdx.x;
    const int w = tid >> 5, l = tid & 31;
    float v[4];
#pragma unroll
    for (int i = 0; i < 4; i++) v[i] = p[tid + i * 128];
    float m = fmaxf(fmaxf(v[0], v[1]), fmaxf(v[2], v[3]));
#pragma unroll
    for (int o = 16; o; o >>= 1) m = fmaxf(m, __shfl_xor_sync(0xffffffffu, m, o));
    __shared__ float red[4], red2[4];
    if (!l) red[w] = m;
    __syncthreads();
    m = fmaxf(fmaxf(red[0], red[1]), fmaxf(red[2], red[3]));
    float s = 0.f;
#pragma unroll
    for (int i = 0; i < 4; i++) { v[i] = __expf(v[i] - m); s += v[i]; }
#pragma unroll
    for (int o = 16; o; o >>= 1) s += __shfl_xor_sync(0xffffffffu, s, o);
    if (!l) red2[w] = s;
    __syncthreads();
    s = red2[0] + red2[1] + red2[2] + red2[3];
    float inv = 1.f / s;
#pragma unroll
    for (int i = 0; i < 4; i++) p[tid + i * 128] = v[i] * inv;
}

// ---------------- out = attn @ v -------------------------------------------
__global__ void out_kernel(float* __restrict__ out) {
    __shared__ float As[16][64];
    __shared__ float Bs[16][64];
    const int tid = threadIdx.x;
    const int tx = tid & 15, ty = tid >> 4;
    const int b = blockIdx.z;
    const int m0 = blockIdx.y * 64, n0 = blockIdx.x * 64;
    const float* attn = g_dots + (size_t)b * TT * TT;
    const float* v = g_qkv + (size_t)b * TT * 768 + 2 * INNER;
    float acc[4][4] = {};
    for (int k0 = 0; k0 < TT; k0 += 16) {
#pragma unroll
        for (int i = 0; i < 4; i++) {
            int idx = tid + i * 256;
            int row = idx >> 4, kk = idx & 15;
            As[kk][row] = attn[(size_t)(m0 + row) * TT + k0 + kk];
            int bk = idx >> 6, bn = idx & 63;
            Bs[bk][bn] = v[(size_t)(k0 + bk) * 768 + n0 + bn];
        }
        __syncthreads();
#pragma unroll
        for (int kk = 0; kk < 16; kk++) {
            float a[4], bb[4];
#pragma unroll
            for (int i = 0; i < 4; i++) { a[i] = As[kk][ty * 4 + i]; bb[i] = Bs[kk][tx * 4 + i]; }
#pragma unroll
            for (int i = 0; i < 4; i++)
#pragma unroll
                for (int j = 0; j < 4; j++) acc[i][j] = fmaf(a[i], bb[j], acc[i][j]);
        }
        __syncthreads();
    }
#pragma unroll
    for (int i = 0; i < 4; i++)
#pragma unroll
        for (int j = 0; j < 4; j++)
            out[(size_t)(b * TT + m0 + ty * 4 + i) * INNER + n0 + tx * 4 + j] = acc[i][j];
}

// ---------------- launch ----------------------------------------------------
extern "C" void kernel_launch(void* const* d_in, const int* in_sizes, int n_in,
                              void* d_out, int out_size) {
    const float* x     = (const float*)d_in[0];
    const float* r     = (const float*)d_in[1];
    const float* w1    = (const float*)d_in[2];
    const float* b1    = (const float*)d_in[3];
    const float* g1    = (const float*)d_in[4];
    const float* be1   = (const float*)d_in[5];
    const float* m1    = (const float*)d_in[6];
    const float* v1    = (const float*)d_in[7];
    const float* w2    = (const float*)d_in[8];
    const float* b2    = (const float*)d_in[9];
    const float* g2    = (const float*)d_in[10];
    const float* be2   = (const float*)d_in[11];
    const float* m2    = (const float*)d_in[12];
    const float* v2    = (const float*)d_in[13];
    const float* w_qkv = (const float*)d_in[14];
    float* out = (float*)d_out;

    setup_kernel<<<1, 256>>>(w1, b1, g1, be1, m1, v1, w2, b2, g2, be2, m2, v2);

    int smem_bytes = (HID * TT + TPR * HID + HID) * (int)sizeof(float);
    cudaFuncSetAttribute(fused_tpr_kernel, cudaFuncAttributeMaxDynamicSharedMemorySize, smem_bytes);
    fused_tpr_kernel<<<BD * TT, 256, smem_bytes>>>(r, x);

    qkv_kernel<<<dim3(768 / 64, 1024 / 64), 256>>>(w_qkv);
    dots_kernel<<<dim3(TT / 64, TT / 64, BD), 256>>>();
    softmax_kernel<<<BD * TT, 128>>>();
    out_kernel<<<dim3(INNER / 64, TT / 64, BD), 256>>>(out);
}

// round 4
// speedup vs baseline: 1.2366x; 1.2366x over previous
#include <cuda_runtime.h>
#include <cuda_bf16.h>
#include <cstdint>

#define TT 512
#define BD 2
#define TOK 256
#define TPR 12
#define HID 32
#define INNER 256
#define ATT_SCALE 0.0625f
#define BN_EPS 1e-5f

// ---------------- scratch (device globals: no allocation allowed) ----------
__device__ float g_w1f[TPR * HID];
__device__ float g_c1[HID];
__device__ float g_c2[TOK];
__device__ uint32_t g_w2bhi[TOK * 16];   // w2^T, BN-folded, bf16-hi pairs [n][kpair]
__device__ uint32_t g_w2blo[TOK * 16];   // bf16-lo pairs
__device__ float g_xb[BD * TT * TOK];
__device__ float g_qkv[BD * TT * 3 * INNER];
__device__ float g_dots[BD * TT * TT];

__device__ __forceinline__ unsigned short bf_bits(__nv_bfloat16 v) {
    return *reinterpret_cast<unsigned short*>(&v);
}
__device__ __forceinline__ uint32_t pack_bf2(float a, float b) {
    __nv_bfloat16 x = __float2bfloat16(a), y = __float2bfloat16(b);
    return (uint32_t)bf_bits(x) | ((uint32_t)bf_bits(y) << 16);
}

// mma.sync m16n8k16 row.col f32.bf16.bf16.f32 (baseline PTX, works on sm_103)
__device__ __forceinline__ void mma16816(float* d, const uint32_t* a, const uint32_t* b) {
    asm volatile(
        "mma.sync.aligned.m16n8k16.row.col.f32.bf16.bf16.f32 "
        "{%0,%1,%2,%3}, {%4,%5,%6,%7}, {%8,%9}, {%0,%1,%2,%3};"
        : "+f"(d[0]), "+f"(d[1]), "+f"(d[2]), "+f"(d[3])
        : "r"(a[0]), "r"(a[1]), "r"(a[2]), "r"(a[3]), "r"(b[0]), "r"(b[1]));
}

// ---------------- setup: fold BN into weights --------------------------------
__global__ void setup_kernel(const float* __restrict__ w1, const float* __restrict__ b1,
                             const float* __restrict__ g1, const float* __restrict__ be1,
                             const float* __restrict__ m1, const float* __restrict__ v1,
                             const float* __restrict__ w2, const float* __restrict__ b2,
                             const float* __restrict__ g2, const float* __restrict__ be2,
                             const float* __restrict__ m2, const float* __restrict__ v2) {
    __shared__ float A1s[HID], A2s[TOK];
    int tid = threadIdx.x;
    if (tid < HID) {
        float a = g1[tid] * rsqrtf(v1[tid] + BN_EPS);
        A1s[tid] = a;
        g_c1[tid] = (b1[tid] - m1[tid]) * a + be1[tid];
    }
    if (tid < TOK) {
        float a = g2[tid] * rsqrtf(v2[tid] + BN_EPS);
        A2s[tid] = a;
        g_c2[tid] = (b2[tid] - m2[tid]) * a + be2[tid];
    }
    __syncthreads();
    for (int i = tid; i < TPR * HID; i += blockDim.x) g_w1f[i] = w1[i] * A1s[i % HID];
    // w2^T pairs: entry i -> n = i>>4, kpair p = i&15 (h = 2p, 2p+1)
    for (int i = tid; i < TOK * 16; i += blockDim.x) {
        int n = i >> 4, p = i & 15;
        float wa = w2[(2 * p) * TOK + n] * A2s[n];
        float wb = w2[(2 * p + 1) * TOK + n] * A2s[n];
        __nv_bfloat16 ha = __float2bfloat16(wa), hb = __float2bfloat16(wb);
        float la = wa - __bfloat162float(ha), lb = wb - __bfloat162float(hb);
        g_w2bhi[i] = (uint32_t)bf_bits(ha) | ((uint32_t)bf_bits(hb) << 16);
        g_w2blo[i] = pack_bf2(la, lb);
    }
}

// ---------------- fused TPR MLP (HMMA) + max + (x+bias) ---------------------
// One block per (b,s). Phase A: h1 (relu'd) as bf16 hi/lo pairs in smem.
// Phase B: split-bf16 mma.sync; per-column max folded in registers.
#define H1_STRIDE 17   // u32 pairs per row (16 + 1 pad) -> conflict-free frags
extern __shared__ uint32_t sm_u[];
__global__ __launch_bounds__(256, 2)
void fused_tpr_kernel(const float* __restrict__ r, const float* __restrict__ x) {
    uint32_t* smHi = sm_u;                      // [512][17]
    uint32_t* smLo = sm_u + TT * H1_STRIDE;     // [512][17]
    uint32_t* smBhi = smLo + TT * H1_STRIDE;    // [256][16]
    uint32_t* smBlo = smBhi + TOK * 16;         // [256][16]
    __shared__ float W1s[TPR * HID], C1s[HID];
    const int tid = threadIdx.x;
    const int bs = blockIdx.x;

    for (int i = tid; i < TPR * HID; i += 256) W1s[i] = g_w1f[i];
    if (tid < HID) C1s[tid] = g_c1[tid];
    for (int i = tid; i < TOK * 16; i += 256) { smBhi[i] = g_w2bhi[i]; smBlo[i] = g_w2blo[i]; }
    __syncthreads();

    // Phase A: stage-1 MLP, 2 t-rows per thread, split to bf16 hi/lo pairs
    const float* rbase = r + (size_t)bs * TT * TPR;
#pragma unroll
    for (int tt = 0; tt < 2; tt++) {
        int t = tid + tt * 256;
        float rv[TPR];
#pragma unroll
        for (int d = 0; d < TPR; d++) rv[d] = rbase[(size_t)t * TPR + d];
        float hv[HID];
#pragma unroll
        for (int h = 0; h < HID; h++) {
            float acc = C1s[h];
#pragma unroll
            for (int d = 0; d < TPR; d++) acc = fmaf(rv[d], W1s[d * HID + h], acc);
            hv[h] = fmaxf(acc, 0.f);
        }
#pragma unroll
        for (int p = 0; p < 16; p++) {
            float a = hv[2 * p], b = hv[2 * p + 1];
            __nv_bfloat16 ha = __float2bfloat16(a), hb = __float2bfloat16(b);
            smHi[t * H1_STRIDE + p] = (uint32_t)bf_bits(ha) | ((uint32_t)bf_bits(hb) << 16);
            smLo[t * H1_STRIDE + p] = pack_bf2(a - __bfloat162float(ha), b - __bfloat162float(hb));
        }
    }
    __syncthreads();

    // Phase B: warp w owns cols [32w, 32w+32); B frags cached in registers.
    const int wid = tid >> 5, lane = tid & 31;
    const int g = lane >> 2, tig = lane & 3;
    const int nb = wid * 32;
    uint32_t Bh[4][4], Bl[4][4];   // [n-subtile][kstep*2 + reg]
#pragma unroll
    for (int sub = 0; sub < 4; sub++) {
        int n = nb + sub * 8 + g;
#pragma unroll
        for (int s = 0; s < 2; s++) {
            Bh[sub][s * 2 + 0] = smBhi[n * 16 + tig + 8 * s];
            Bh[sub][s * 2 + 1] = smBhi[n * 16 + tig + 4 + 8 * s];
            Bl[sub][s * 2 + 0] = smBlo[n * 16 + tig + 8 * s];
            Bl[sub][s * 2 + 1] = smBlo[n * 16 + tig + 4 + 8 * s];
        }
    }
    float mx[4][2];
#pragma unroll
    for (int sub = 0; sub < 4; sub++) { mx[sub][0] = -3.4e38f; mx[sub][1] = -3.4e38f; }

    for (int mi = 0; mi < 32; mi++) {
        float acc[4][4];
#pragma unroll
        for (int sub = 0; sub < 4; sub++)
#pragma unroll
            for (int j = 0; j < 4; j++) acc[sub][j] = 0.f;
        const int r0 = mi * 16 + g;
#pragma unroll
        for (int s = 0; s < 2; s++) {
            uint32_t Ah[4], Al[4];
            int o0 = r0 * H1_STRIDE + tig + 8 * s;
            int o1 = (r0 + 8) * H1_STRIDE + tig + 8 * s;
            Ah[0] = smHi[o0];     Ah[1] = smHi[o1];
            Ah[2] = smHi[o0 + 4]; Ah[3] = smHi[o1 + 4];
            Al[0] = smLo[o0];     Al[1] = smLo[o1];
            Al[2] = smLo[o0 + 4]; Al[3] = smLo[o1 + 4];
#pragma unroll
            for (int sub = 0; sub < 4; sub++) {
                mma16816(acc[sub], Ah, &Bh[sub][s * 2]);
                mma16816(acc[sub], Al, &Bh[sub][s * 2]);
                mma16816(acc[sub], Ah, &Bl[sub][s * 2]);
            }
        }
#pragma unroll
        for (int sub = 0; sub < 4; sub++) {
            mx[sub][0] = fmaxf(mx[sub][0], fmaxf(acc[sub][0], acc[sub][2]));
            mx[sub][1] = fmaxf(mx[sub][1], fmaxf(acc[sub][1], acc[sub][3]));
        }
    }
    // reduce over row-groups (lanes with same tig), then write xb
#pragma unroll
    for (int sub = 0; sub < 4; sub++) {
#pragma unroll
        for (int j = 0; j < 2; j++) {
            float v = mx[sub][j];
            v = fmaxf(v, __shfl_xor_sync(0xffffffffu, v, 4));
            v = fmaxf(v, __shfl_xor_sync(0xffffffffu, v, 8));
            v = fmaxf(v, __shfl_xor_sync(0xffffffffu, v, 16));
            if (lane < 4) {
                int c = nb + sub * 8 + 2 * lane + j;
                g_xb[(size_t)bs * TOK + c] = x[(size_t)bs * TOK + c] + fmaxf(v + g_c2[c], 0.f);
            }
        }
    }
}

// ---------------- qkv = xb @ w_qkv  [1024,256]x[256,768] --------------------
__global__ void qkv_kernel(const float* __restrict__ w_qkv) {
    __shared__ float As[16][64];
    __shared__ float Bs[16][64];
    const int tid = threadIdx.x;
    const int tx = tid & 15, ty = tid >> 4;
    const int m0 = blockIdx.y * 64, n0 = blockIdx.x * 64;
    float acc[4][4] = {};
    for (int k0 = 0; k0 < TOK; k0 += 16) {
#pragma unroll
        for (int i = 0; i < 4; i++) {
            int idx = tid + i * 256;
            int row = idx >> 4, kk = idx & 15;
            As[kk][row] = g_xb[(size_t)(m0 + row) * TOK + k0 + kk];
            int bk = idx >> 6, bn = idx & 63;
            Bs[bk][bn] = w_qkv[(size_t)(k0 + bk) * 768 + n0 + bn];
        }
        __syncthreads();
#pragma unroll
        for (int kk = 0; kk < 16; kk++) {
            float a[4], b[4];
#pragma unroll
            for (int i = 0; i < 4; i++) { a[i] = As[kk][ty * 4 + i]; b[i] = Bs[kk][tx * 4 + i]; }
#pragma unroll
            for (int i = 0; i < 4; i++)
#pragma unroll
                for (int j = 0; j < 4; j++) acc[i][j] = fmaf(a[i], b[j], acc[i][j]);
        }
        __syncthreads();
    }
#pragma unroll
    for (int i = 0; i < 4; i++)
#pragma unroll
        for (int j = 0; j < 4; j++)
            g_qkv[(size_t)(m0 + ty * 4 + i) * 768 + n0 + tx * 4 + j] = acc[i][j];
}

// ---------------- dots = q @ k^T * scale ------------------------------------
__global__ void dots_kernel() {
    __shared__ float As[16][64];
    __shared__ float Bs[16][64];
    const int tid = threadIdx.x;
    const int tx = tid & 15, ty = tid >> 4;
    const int b = blockIdx.z;
    const int m0 = blockIdx.x * 64, n0 = blockIdx.y * 64;
    const float* q = g_qkv + (size_t)b * TT * 768;
    const float* k = g_qkv + (size_t)b * TT * 768 + INNER;
    float acc[4][4] = {};
    for (int k0 = 0; k0 < INNER; k0 += 16) {
#pragma unroll
        for (int i = 0; i < 4; i++) {
            int idx = tid + i * 256;
            int row = idx >> 4, kk = idx & 15;
            As[kk][row] = q[(size_t)(m0 + row) * 768 + k0 + kk];
            Bs[kk][row] = k[(size_t)(n0 + row) * 768 + k0 + kk];
        }
        __syncthreads();
#pragma unroll
        for (int kk = 0; kk < 16; kk++) {
            float a[4], bb[4];
#pragma unroll
            for (int i = 0; i < 4; i++) { a[i] = As[kk][ty * 4 + i]; bb[i] = Bs[kk][tx * 4 + i]; }
#pragma unroll
            for (int i = 0; i < 4; i++)
#pragma unroll
                for (int j = 0; j < 4; j++) acc[i][j] = fmaf(a[i], bb[j], acc[i][j]);
        }
        __syncthreads();
    }
    float* dst = g_dots + (size_t)b * TT * TT;
#pragma unroll
    for (int i = 0; i < 4; i++)
#pragma unroll
        for (int j = 0; j < 4; j++)
            dst[(size_t)(m0 + ty * 4 + i) * TT + n0 + tx * 4 + j] = acc[i][j] * ATT_SCALE;
}

// ---------------- row softmax over 512 --------------------------------------
__global__ void softmax_kernel() {
    const int row = blockIdx.x;
    float* p = g_dots + (size_t)row * TT;
    const int tid = threadIdx.x;
    const int w = tid >> 5, l = tid & 31;
    float v[4];
#pragma unroll
    for (int i = 0; i < 4; i++) v[i] = p[tid + i * 128];
    float m = fmaxf(fmaxf(v[0], v[1]), fmaxf(v[2], v[3]));
#pragma unroll
    for (int o = 16; o; o >>= 1) m = fmaxf(m, __shfl_xor_sync(0xffffffffu, m, o));
    __shared__ float red[4], red2[4];
    if (!l) red[w] = m;
    __syncthreads();
    m = fmaxf(fmaxf(red[0], red[1]), fmaxf(red[2], red[3]));
    float s = 0.f;
#pragma unroll
    for (int i = 0; i < 4; i++) { v[i] = __expf(v[i] - m); s += v[i]; }
#pragma unroll
    for (int o = 16; o; o >>= 1) s += __shfl_xor_sync(0xffffffffu, s, o);
    if (!l) red2[w] = s;
    __syncthreads();
    s = red2[0] + red2[1] + red2[2] + red2[3];
    float inv = 1.f / s;
#pragma unroll
    for (int i = 0; i < 4; i++) p[tid + i * 128] = v[i] * inv;
}

// ---------------- out = attn @ v ---------------------------------------------
__global__ void out_kernel(float* __restrict__ out) {
    __shared__ float As[16][64];
    __shared__ float Bs[16][64];
    const int tid = threadIdx.x;
    const int tx = tid & 15, ty = tid >> 4;
    const int b = blockIdx.z;
    const int m0 = blockIdx.y * 64, n0 = blockIdx.x * 64;
    const float* attn = g_dots + (size_t)b * TT * TT;
    const float* v = g_qkv + (size_t)b * TT * 768 + 2 * INNER;
    float acc[4][4] = {};
    for (int k0 = 0; k0 < TT; k0 += 16) {
#pragma unroll
        for (int i = 0; i < 4; i++) {
            int idx = tid + i * 256;
            int row = idx >> 4, kk = idx & 15;
            As[kk][row] = attn[(size_t)(m0 + row) * TT + k0 + kk];
            int bk = idx >> 6, bn = idx & 63;
            Bs[bk][bn] = v[(size_t)(k0 + bk) * 768 + n0 + bn];
        }
        __syncthreads();
#pragma unroll
        for (int kk = 0; kk < 16; kk++) {
            float a[4], bb[4];
#pragma unroll
            for (int i = 0; i < 4; i++) { a[i] = As[kk][ty * 4 + i]; bb[i] = Bs[kk][tx * 4 + i]; }
#pragma unroll
            for (int i = 0; i < 4; i++)
#pragma unroll
                for (int j = 0; j < 4; j++) acc[i][j] = fmaf(a[i], bb[j], acc[i][j]);
        }
        __syncthreads();
    }
#pragma unroll
    for (int i = 0; i < 4; i++)
#pragma unroll
        for (int j = 0; j < 4; j++)
            out[(size_t)(b * TT + m0 + ty * 4 + i) * INNER + n0 + tx * 4 + j] = acc[i][j];
}

// ---------------- launch ------------------------------------------------------
extern "C" void kernel_launch(void* const* d_in, const int* in_sizes, int n_in,
                              void* d_out, int out_size) {
    const float* x     = (const float*)d_in[0];
    const float* r     = (const float*)d_in[1];
    const float* w1    = (const float*)d_in[2];
    const float* b1    = (const float*)d_in[3];
    const float* g1    = (const float*)d_in[4];
    const float* be1   = (const float*)d_in[5];
    const float* m1    = (const float*)d_in[6];
    const float* v1    = (const float*)d_in[7];
    const float* w2    = (const float*)d_in[8];
    const float* b2    = (const float*)d_in[9];
    const float* g2    = (const float*)d_in[10];
    const float* be2   = (const float*)d_in[11];
    const float* m2    = (const float*)d_in[12];
    const float* v2    = (const float*)d_in[13];
    const float* w_qkv = (const float*)d_in[14];
    float* out = (float*)d_out;

    setup_kernel<<<1, 256>>>(w1, b1, g1, be1, m1, v1, w2, b2, g2, be2, m2, v2);

    int smem_bytes = (TT * H1_STRIDE * 2 + TOK * 16 * 2) * (int)sizeof(uint32_t); // 102400
    cudaFuncSetAttribute(fused_tpr_kernel, cudaFuncAttributeMaxDynamicSharedMemorySize, smem_bytes);
    fused_tpr_kernel<<<BD * TT, 256, smem_bytes>>>(r, x);

    qkv_kernel<<<dim3(768 / 64, 1024 / 64), 256>>>(w_qkv);
    dots_kernel<<<dim3(TT / 64, TT / 64, BD), 256>>>();
    softmax_kernel<<<BD * TT, 128>>>();
    out_kernel<<<dim3(INNER / 64, TT / 64, BD), 256>>>(out);
}